// round 7
// baseline (speedup 1.0000x reference)
#include <cuda_runtime.h>
#include <stdint.h>

// out[b][r] = prod_{i=0..7} v(b,i,mf[r][i]);  v = 1.0 if idx==-1 else x[b][i][idx]
// Fused single kernel. Pair tables (4 x 25 per batch), warp-autonomous:
// each warp owns a fixed 128-rule tile (offsets from mf in a one-time
// prologue) and builds PRIVATE tables for 8-batch groups in its own smem
// slice. DOUBLE-BUFFERED: build group g+1 into buf^1 while computing group
// g from buf^0 -> the STS->LDS dependency spans a full iteration, off the
// critical path. One __syncwarp per iteration. Gathers read 25 consecutive
// words (conflict-free); build STS addresses 100b+25p+e form a bijection
// mod 32 (conflict-free). No block barriers.

#define THREADS 1024
#define NSM 148

__global__ __launch_bounds__(THREADS, 1)
void fire_kernel(const float* __restrict__ x, const int* __restrict__ mf,
                 float* __restrict__ out, int n_rules, int n_groups) {
    extern __shared__ float ptab[];

    const int lane = threadIdx.x & 31;
    const int wid  = threadIdx.x >> 5;
    float* buf0 = ptab + wid * 1600;        // buffer A: 8 batches x stride 100
    float* buf1 = buf0 + 800;               // buffer B

    const int tiles    = n_rules >> 7;                   // 16
    const int stream   = wid * NSM + (int)blockIdx.x;    // 0..4735
    const int tile     = stream & (tiles - 1);
    const int gidx     = stream >> 4;                    // 0..295
    const int nstreams = (NSM * (THREADS / 32)) >> 4;    // 296
    const int r0       = tile << 7;

    // ---- prologue: packed pair-offsets for this warp's 128 rules ----
    int c0[4], c1[4], c2[4], c3[4];
    {
        const int4* m4 = (const int4*)(mf + (size_t)(r0 + 4 * lane) * 8);
#pragma unroll
        for (int q = 0; q < 4; ++q) {
            int4 lo = m4[2 * q + 0];
            int4 hi = m4[2 * q + 1];
            int* dst = (q == 0) ? c0 : (q == 1) ? c1 : (q == 2) ? c2 : c3;
            dst[0] = 0 * 25 + (lo.x + 1) * 5 + (lo.y + 1);
            dst[1] = 1 * 25 + (lo.z + 1) * 5 + (lo.w + 1);
            dst[2] = 2 * 25 + (hi.x + 1) * 5 + (hi.y + 1);
            dst[3] = 3 * 25 + (hi.z + 1) * 5 + (hi.w + 1);
        }
    }

    // lane -> (batch slot b = lane>>2, pair p = lane&3)
    const int bslot = lane >> 2;
    const int pslot = lane & 3;
    const size_t xoff = (size_t)bslot * 32 + pslot * 8;

    auto ldx = [&](int g, float4& xa, float4& xc) {
        if (g < n_groups) {
            const float4* p4 = (const float4*)(x + (size_t)g * 256 + xoff);
            xa = p4[0];
            xc = p4[1];
        }
    };

    auto build = [&](float* buf, const float4& xa, const float4& xc) {
        float Av[5] = {1.0f, xa.x, xa.y, xa.z, xa.w};
        float Cv[5] = {1.0f, xc.x, xc.y, xc.z, xc.w};
        float* dst = buf + bslot * 100 + pslot * 25;
#pragma unroll
        for (int a = 0; a < 5; ++a)
#pragma unroll
            for (int c = 0; c < 5; ++c)
                dst[a * 5 + c] = Av[a] * Cv[c];
    };

    int g = gidx;
    if (g >= n_groups) return;

    // prologue: build first group into buf0, prefetch next group's x
    float4 xa, xc, nxa, nxc;
    ldx(g, xa, xc);
    build(buf0, xa, xc);
    ldx(g + nstreams, nxa, nxc);
    __syncwarp();

    float* cbuf = buf0;   // compute buffer
    float* bbuf = buf1;   // build buffer

    for (; g < n_groups; g += nstreams) {
        // build NEXT group's tables into the other buffer (no consumer
        // until after the end-of-iteration syncwarp -> latency hidden)
        if (g + nstreams < n_groups) {
            build(bbuf, nxa, nxc);
            ldx(g + 2 * nstreams, nxa, nxc);
        }

        // ---- compute 8 batches x 4 rules/lane from current buffer ----
        float* o = out + (size_t)(g * 8) * n_rules + r0 + 4 * lane;
        const float* pb = cbuf;
#pragma unroll 4
        for (int b = 0; b < 8; ++b) {
            float4 v;
            v.x = (pb[c0[0]] * pb[c0[1]]) * (pb[c0[2]] * pb[c0[3]]);
            v.y = (pb[c1[0]] * pb[c1[1]]) * (pb[c1[2]] * pb[c1[3]]);
            v.z = (pb[c2[0]] * pb[c2[1]]) * (pb[c2[2]] * pb[c2[3]]);
            v.w = (pb[c3[0]] * pb[c3[1]]) * (pb[c3[2]] * pb[c3[3]]);
            *(float4*)o = v;
            pb += 100;
            o  += n_rules;
        }

        __syncwarp();   // order this iter's STS before next iter's LDS
        float* t = cbuf; cbuf = bbuf; bbuf = t;
    }
}

extern "C" void kernel_launch(void* const* d_in, const int* in_sizes, int n_in,
                              void* d_out, int out_size) {
    const float* x  = (const float*)d_in[0];
    const int*   mf = (const int*)d_in[1];
    float* out = (float*)d_out;

    const int n_rules  = in_sizes[1] / 8;     // 2048
    const int B        = in_sizes[0] / 32;    // 8192
    const int n_groups = B / 8;               // 1024

    size_t smem = 32 * 1600 * sizeof(float);  // 204.8 KB (double-buffered)
    cudaFuncSetAttribute(fire_kernel, cudaFuncAttributeMaxDynamicSharedMemorySize, (int)smem);
    fire_kernel<<<NSM, THREADS, smem>>>(x, mf, out, n_rules, n_groups);
}